// round 5
// baseline (speedup 1.0000x reference)
#include <cuda_runtime.h>
#include <math.h>
#include <cstdint>

#define N_NODES 100000
#define E_EDGES 1600000
#define HD 128
#define OD 40
#define NLAYERS 4
#define SCALE 0.08838834764831845f  // 1/sqrt(128)

// ---------------- device scratch (no allocations allowed) ----------------
__device__ float g_h[(size_t)N_NODES * HD];
__device__ float g_q[(size_t)N_NODES * HD];
__device__ float g_k[(size_t)N_NODES * HD];
__device__ float g_v[(size_t)N_NODES * HD];
__device__ float g_s[(size_t)N_NODES * HD];
__device__ int   g_deg[N_NODES];
__device__ int   g_rowstart[N_NODES + 1];
__device__ int   g_cursor[N_NODES];
__device__ int   g_esrc[E_EDGES];

// ---------------- packed fp32x2 FMA (Blackwell FFMA2, PTX-only) ----------------
__device__ __forceinline__ void ffma2(unsigned long long& acc,
                                      unsigned long long a, unsigned long long b) {
    asm("fma.rn.f32x2 %0, %1, %2, %0;" : "+l"(acc) : "l"(a), "l"(b));
}
__device__ __forceinline__ float2 unpack2(unsigned long long p) {
    float2 f;
    asm("mov.b64 {%0, %1}, %2;" : "=f"(f.x), "=f"(f.y) : "l"(p));
    return f;
}
__device__ __forceinline__ unsigned long long dup_f32(float a) {
    unsigned long long u = __float_as_uint(a);
    return u | (u << 32);
}

// ==================== GEMM via f32x2: C[rows,128] = A @ W + bias ====================
// 128x128 tile, 256 threads, 8x8 outputs/thread as 8x4 f32x2 pairs (paired columns).
// A duplicated in SMEM so the broadcast operand is a natural 64-bit (a,a) load.
#define GP_W 132                       // Ws pitch (floats): keeps float4 alignment
#define GP_A 258                       // Asd pitch (floats): ty-rows 8256B apart -> bank+16
#define GEMM_SMEM (128 * GP_A * 4 + 128 * GP_W * 4)   // 132096 + 67584 = 199680 B

__global__ __launch_bounds__(256, 1)
void gemm_f32x2(const float* __restrict__ A, const float* __restrict__ W,
                const float* __restrict__ bias, float* __restrict__ C, int nrows)
{
    extern __shared__ float sm[];
    float* Asd = sm;                   // 128 x GP_A, value-duplicated pairs
    float* Ws  = sm + 128 * GP_A;      // 128 x GP_W

    const int tid  = threadIdx.x;
    const int row0 = blockIdx.x * 128;

    // ---- fill tiles: 4096 float4 loads each of A and W, 16 per thread ----
    #pragma unroll
    for (int c = 0; c < 16; c++) {
        int idx = c * 256 + tid;
        int r   = idx >> 5;
        int c4  = (idx & 31) * 4;
        float4 w4 = *reinterpret_cast<const float4*>(&W[r * 128 + c4]);
        *reinterpret_cast<float4*>(&Ws[r * GP_W + c4]) = w4;
        int ar = row0 + r;
        float4 a4 = make_float4(0.f, 0.f, 0.f, 0.f);
        if (ar < nrows) a4 = *reinterpret_cast<const float4*>(&A[(size_t)ar * 128 + c4]);
        unsigned long long* dp =
            reinterpret_cast<unsigned long long*>(&Asd[r * GP_A + 2 * c4]);
        dp[0] = dup_f32(a4.x);
        dp[1] = dup_f32(a4.y);
        dp[2] = dup_f32(a4.z);
        dp[3] = dup_f32(a4.w);
    }
    __syncthreads();

    const int tx = tid & 15, ty = tid >> 4;
    const int r0 = ty * 8, c0 = tx * 8;

    unsigned long long acc[8][4];
    #pragma unroll
    for (int i = 0; i < 8; i++)
        #pragma unroll
        for (int j = 0; j < 4; j++) acc[i][j] = 0ull;

    #pragma unroll 4
    for (int k = 0; k < 128; k++) {
        unsigned long long ap[8];
        #pragma unroll
        for (int i = 0; i < 8; i++)
            ap[i] = *reinterpret_cast<const unsigned long long*>(
                        &Asd[(r0 + i) * GP_A + 2 * k]);
        ulonglong2 b01 = *reinterpret_cast<const ulonglong2*>(&Ws[k * GP_W + c0]);
        ulonglong2 b23 = *reinterpret_cast<const ulonglong2*>(&Ws[k * GP_W + c0 + 4]);
        unsigned long long bp[4] = {b01.x, b01.y, b23.x, b23.y};
        #pragma unroll
        for (int i = 0; i < 8; i++)
            #pragma unroll
            for (int j = 0; j < 4; j++)
                ffma2(acc[i][j], ap[i], bp[j]);
    }

    float bb[8];
    #pragma unroll
    for (int j = 0; j < 8; j++) bb[j] = bias[c0 + j];

    #pragma unroll
    for (int i = 0; i < 8; i++) {
        int r = row0 + r0 + i;
        if (r < nrows) {
            float2 p0 = unpack2(acc[i][0]);
            float2 p1 = unpack2(acc[i][1]);
            float2 p2 = unpack2(acc[i][2]);
            float2 p3 = unpack2(acc[i][3]);
            float4 o0 = make_float4(p0.x + bb[0], p0.y + bb[1], p1.x + bb[2], p1.y + bb[3]);
            float4 o1 = make_float4(p2.x + bb[4], p2.y + bb[5], p3.x + bb[6], p3.y + bb[7]);
            *reinterpret_cast<float4*>(&C[(size_t)r * 128 + c0])     = o0;
            *reinterpret_cast<float4*>(&C[(size_t)r * 128 + c0 + 4]) = o1;
        }
    }
}

// ==================== CSR build (once per launch) ====================
__global__ void csr_zero(int* __restrict__ deg) {
    int n = blockIdx.x * blockDim.x + threadIdx.x;
    if (n < N_NODES) deg[n] = 0;
}

__global__ __launch_bounds__(256)
void csr_count(const int* __restrict__ ei, int* __restrict__ deg) {
    int e = blockIdx.x * blockDim.x + threadIdx.x;
    if (e >= E_EDGES) return;
    atomicAdd(&deg[ei[E_EDGES + e]], 1);
}

__global__ __launch_bounds__(1024)
void csr_scan(const int* __restrict__ deg, int* __restrict__ rowstart,
              int* __restrict__ cursor)
{
    __shared__ int wsum[32];
    __shared__ int carry_sh;
    const int tid  = threadIdx.x;
    const int lane = tid & 31;
    const int wid  = tid >> 5;
    if (tid == 0) carry_sh = 0;
    __syncthreads();

    for (int base = 0; base < N_NODES; base += 1024) {
        int cv = carry_sh;
        int n  = base + tid;
        int v  = (n < N_NODES) ? deg[n] : 0;
        int x = v;
        #pragma unroll
        for (int o = 1; o < 32; o <<= 1) {
            int y = __shfl_up_sync(0xFFFFFFFFu, x, o);
            if (lane >= o) x += y;
        }
        if (lane == 31) wsum[wid] = x;
        __syncthreads();
        if (wid == 0) {
            int w = wsum[lane];
            #pragma unroll
            for (int o = 1; o < 32; o <<= 1) {
                int y = __shfl_up_sync(0xFFFFFFFFu, w, o);
                if (lane >= o) w += y;
            }
            wsum[lane] = w;
        }
        __syncthreads();
        int incl = x + (wid ? wsum[wid - 1] : 0);
        int excl = cv + incl - v;
        if (n < N_NODES) { rowstart[n] = excl; cursor[n] = excl; }
        __syncthreads();
        if (tid == 1023) carry_sh = cv + incl;
        __syncthreads();
    }
    if (tid == 0) rowstart[N_NODES] = E_EDGES;
}

__global__ __launch_bounds__(256)
void csr_scatter(const int* __restrict__ ei, int* __restrict__ cursor,
                 int* __restrict__ esrc)
{
    int e = blockIdx.x * blockDim.x + threadIdx.x;
    if (e >= E_EDGES) return;
    int dst  = ei[E_EDGES + e];
    int slot = atomicAdd(&cursor[dst], 1);
    esrc[slot] = ei[e];
}

// ==================== fused per-node attention layer ====================
__global__ __launch_bounds__(256)
void gat_node(const int* __restrict__ rowstart, const int* __restrict__ esrc,
              const float* __restrict__ q, const float* __restrict__ k,
              const float* __restrict__ v, const float* __restrict__ skip,
              float* __restrict__ hout, int apply_elu)
{
    const int wid  = threadIdx.x >> 5;
    const int lane = threadIdx.x & 31;
    const int n    = blockIdx.x * 8 + wid;
    if (n >= N_NODES) return;

    const int beg = rowstart[n];
    const int end = rowstart[n + 1];

    float4 q4 = *reinterpret_cast<const float4*>(&q[(size_t)n * 128 + lane * 4]);
    float4 acc = make_float4(0.f, 0.f, 0.f, 0.f);
    float  den = 0.f;

    if (beg < end) {
        int src = __ldg(&esrc[beg]);
        float4 k4 = __ldg(reinterpret_cast<const float4*>(&k[(size_t)src * 128 + lane * 4]));
        float4 v4 = __ldg(reinterpret_cast<const float4*>(&v[(size_t)src * 128 + lane * 4]));
        for (int i = beg; i < end; i++) {
            float4 kc = k4, vc = v4;
            if (i + 1 < end) {
                int s2 = __ldg(&esrc[i + 1]);
                k4 = __ldg(reinterpret_cast<const float4*>(&k[(size_t)s2 * 128 + lane * 4]));
                v4 = __ldg(reinterpret_cast<const float4*>(&v[(size_t)s2 * 128 + lane * 4]));
            }
            float p = q4.x * kc.x + q4.y * kc.y + q4.z * kc.z + q4.w * kc.w;
            #pragma unroll
            for (int off = 16; off > 0; off >>= 1)
                p += __shfl_xor_sync(0xFFFFFFFFu, p, off);
            float e = __expf(p * SCALE);
            den   += e;
            acc.x += e * vc.x; acc.y += e * vc.y;
            acc.z += e * vc.z; acc.w += e * vc.w;
        }
    }

    float4 s4 = *reinterpret_cast<const float4*>(&skip[(size_t)n * 128 + lane * 4]);
    float inv = (beg < end) ? (1.f / den) : 0.f;
    float4 r;
    r.x = acc.x * inv + s4.x;
    r.y = acc.y * inv + s4.y;
    r.z = acc.z * inv + s4.z;
    r.w = acc.w * inv + s4.w;
    if (apply_elu) {
        r.x = r.x > 0.f ? r.x : expm1f(r.x);
        r.y = r.y > 0.f ? r.y : expm1f(r.y);
        r.z = r.z > 0.f ? r.z : expm1f(r.z);
        r.w = r.w > 0.f ? r.w : expm1f(r.w);
    }
    *reinterpret_cast<float4*>(&hout[(size_t)n * 128 + lane * 4]) = r;
}

// ---------------- classifier: out = log_softmax(h @ fcW + fcb) ----------------
__global__ __launch_bounds__(256)
void classifier(const float* __restrict__ h, const float* __restrict__ fcW,
                const float* __restrict__ fcb, float* __restrict__ out)
{
    __shared__ float Wsh[128 * 64];
    __shared__ float hs[8][128];

    int tid = threadIdx.x;
    for (int i = tid; i < 128 * 64; i += 256) {
        int r = i >> 6, c = i & 63;
        Wsh[i] = (c < OD) ? fcW[r * OD + c] : 0.f;
    }
    __syncthreads();

    int wid  = tid >> 5;
    int lane = tid & 31;
    int n    = blockIdx.x * 8 + wid;
    if (n >= N_NODES) return;

    reinterpret_cast<float4*>(hs[wid])[lane] =
        reinterpret_cast<const float4*>(&h[(size_t)n * 128])[lane];
    __syncwarp();

    float acc0 = 0.f, acc1 = 0.f;
    #pragma unroll 8
    for (int k = 0; k < 128; k++) {
        float hv = hs[wid][k];
        acc0 += hv * Wsh[k * 64 + lane];
        acc1 += hv * Wsh[k * 64 + 32 + lane];
    }
    float val0 = acc0 + fcb[lane];
    float val1 = (lane < 8) ? (acc1 + fcb[32 + lane]) : -__int_as_float(0x7F800000);

    float vmax = fmaxf(val0, val1);
    #pragma unroll
    for (int off = 16; off > 0; off >>= 1)
        vmax = fmaxf(vmax, __shfl_xor_sync(0xFFFFFFFFu, vmax, off));

    float s = __expf(val0 - vmax) + ((lane < 8) ? __expf(val1 - vmax) : 0.f);
    #pragma unroll
    for (int off = 16; off > 0; off >>= 1)
        s += __shfl_xor_sync(0xFFFFFFFFu, s, off);

    float lse = vmax + logf(s);
    out[(size_t)n * OD + lane] = val0 - lse;
    if (lane < 8) out[(size_t)n * OD + 32 + lane] = val1 - lse;
}

// ---------------- host launch ----------------
extern "C" void kernel_launch(void* const* d_in, const int* in_sizes, int n_in,
                              void* d_out, int out_size)
{
    const float* x     = (const float*)d_in[0];
    const int*   ei    = (const int*)  d_in[1];
    const float* lin_W = (const float*)d_in[2];
    const float* lin_b = (const float*)d_in[3];
    const float* Wq    = (const float*)d_in[4];
    const float* bq    = (const float*)d_in[5];
    const float* Wk    = (const float*)d_in[6];
    const float* bk    = (const float*)d_in[7];
    const float* Wv    = (const float*)d_in[8];
    const float* bv    = (const float*)d_in[9];
    const float* Wsk   = (const float*)d_in[10];
    const float* bsk   = (const float*)d_in[11];
    const float* fcW   = (const float*)d_in[12];
    const float* fcb   = (const float*)d_in[13];
    float* out = (float*)d_out;

    float *h, *q, *k, *v, *s;
    int *deg, *rowstart, *cursor, *esrc;
    cudaGetSymbolAddress((void**)&h,        g_h);
    cudaGetSymbolAddress((void**)&q,        g_q);
    cudaGetSymbolAddress((void**)&k,        g_k);
    cudaGetSymbolAddress((void**)&v,        g_v);
    cudaGetSymbolAddress((void**)&s,        g_s);
    cudaGetSymbolAddress((void**)&deg,      g_deg);
    cudaGetSymbolAddress((void**)&rowstart, g_rowstart);
    cudaGetSymbolAddress((void**)&cursor,   g_cursor);
    cudaGetSymbolAddress((void**)&esrc,     g_esrc);

    cudaFuncSetAttribute(gemm_f32x2, cudaFuncAttributeMaxDynamicSharedMemorySize, GEMM_SMEM);

    const int GB  = (N_NODES + 127) / 128;
    const int NB  = (N_NODES + 255) / 256;
    const int ETB = (E_EDGES + 255) / 256;
    const int WNB = (N_NODES + 7) / 8;

    // ---- CSR build ----
    csr_zero<<<NB, 256>>>(deg);
    csr_count<<<ETB, 256>>>(ei, deg);
    csr_scan<<<1, 1024>>>(deg, rowstart, cursor);
    csr_scatter<<<ETB, 256>>>(ei, cursor, esrc);

    // ---- input projection ----
    gemm_f32x2<<<GB, 256, GEMM_SMEM>>>(x, lin_W, lin_b, h, N_NODES);

    for (int l = 0; l < NLAYERS; l++) {
        const float* Wq_l = Wq  + (size_t)l * HD * HD;
        const float* Wk_l = Wk  + (size_t)l * HD * HD;
        const float* Wv_l = Wv  + (size_t)l * HD * HD;
        const float* Ws_l = Wsk + (size_t)l * HD * HD;
        const float* bq_l = bq  + (size_t)l * HD;
        const float* bk_l = bk  + (size_t)l * HD;
        const float* bv_l = bv  + (size_t)l * HD;
        const float* bs_l = bsk + (size_t)l * HD;

        gemm_f32x2<<<GB, 256, GEMM_SMEM>>>(h, Wq_l, bq_l, q, N_NODES);
        gemm_f32x2<<<GB, 256, GEMM_SMEM>>>(h, Wk_l, bk_l, k, N_NODES);
        gemm_f32x2<<<GB, 256, GEMM_SMEM>>>(h, Wv_l, bv_l, v, N_NODES);
        gemm_f32x2<<<GB, 256, GEMM_SMEM>>>(h, Ws_l, bs_l, s, N_NODES);

        gat_node<<<WNB, 256>>>(rowstart, esrc, q, k, v, s, h,
                               (l < NLAYERS - 1) ? 1 : 0);
    }

    classifier<<<WNB, 256>>>(h, fcW, fcb, out);
}

// round 8
// speedup vs baseline: 1.3999x; 1.3999x over previous
#include <cuda_runtime.h>
#include <cuda_fp16.h>
#include <math.h>
#include <cstdint>

#define N_NODES 100000
#define E_EDGES 1600000
#define HD 128
#define OD 40
#define NLAYERS 4
#define SCALE 0.08838834764831845f  // 1/sqrt(128)

// ---------------- device scratch (no allocations allowed) ----------------
__device__ float  g_h[(size_t)N_NODES * HD];
__device__ float  g_q[(size_t)N_NODES * HD];
__device__ __half g_k[(size_t)N_NODES * HD];
__device__ __half g_v[(size_t)N_NODES * HD];
__device__ float  g_s[(size_t)N_NODES * HD];
__device__ int    g_deg[N_NODES];
__device__ int    g_rowstart[N_NODES + 1];
__device__ int    g_cursor[N_NODES];
__device__ int    g_esrc[E_EDGES];

// ==================== fused per-layer GEMM ====================
// gridDim.y selects: 0 -> q (fp32), 1 -> k (fp16), 2 -> v (fp16), 3 -> s (fp32).
// Scalar FFMA inner loop (verified at the fp32 roofline, 96.6us/GEMM — do not touch).
#define GPITCH 132
#define GEMM_SMEM (2 * 128 * GPITCH * 4)

__global__ __launch_bounds__(256, 1)
void gemm_layer(const float* __restrict__ A,
                const float* __restrict__ Wq, const float* __restrict__ Wk,
                const float* __restrict__ Wv, const float* __restrict__ Wss,
                const float* __restrict__ bq, const float* __restrict__ bk,
                const float* __restrict__ bv, const float* __restrict__ bss,
                float* __restrict__ outq, __half* __restrict__ outk,
                __half* __restrict__ outv, float* __restrict__ outs, int nrows)
{
    extern __shared__ float sm[];
    float* As = sm;                    // 128 x GPITCH
    float* Ws = sm + 128 * GPITCH;     // 128 x GPITCH

    const int y = blockIdx.y;
    const float* W    = (y == 0) ? Wq : (y == 1) ? Wk : (y == 2) ? Wv : Wss;
    const float* bias = (y == 0) ? bq : (y == 1) ? bk : (y == 2) ? bv : bss;

    const int tid  = threadIdx.x;
    const int row0 = blockIdx.x * 128;

    #pragma unroll
    for (int c = 0; c < 16; c++) {
        int idx = c * 256 + tid;
        int r   = idx >> 5;
        int c4  = (idx & 31) * 4;
        float4 w4 = *reinterpret_cast<const float4*>(&W[r * 128 + c4]);
        *reinterpret_cast<float4*>(&Ws[r * GPITCH + c4]) = w4;
        int ar = row0 + r;
        float4 a4 = make_float4(0.f, 0.f, 0.f, 0.f);
        if (ar < nrows) a4 = *reinterpret_cast<const float4*>(&A[(size_t)ar * 128 + c4]);
        *reinterpret_cast<float4*>(&As[r * GPITCH + c4]) = a4;
    }
    __syncthreads();

    const int tx = tid & 15, ty = tid >> 4;
    const int r0 = ty * 8, c0 = tx * 8;

    float acc[8][8];
    #pragma unroll
    for (int i = 0; i < 8; i++)
        #pragma unroll
        for (int j = 0; j < 8; j++) acc[i][j] = 0.f;

    #pragma unroll 8
    for (int k = 0; k < 128; k++) {
        float a[8];
        #pragma unroll
        for (int i = 0; i < 8; i++) a[i] = As[(r0 + i) * GPITCH + k];
        float4 b0 = *reinterpret_cast<const float4*>(&Ws[k * GPITCH + c0]);
        float4 b1 = *reinterpret_cast<const float4*>(&Ws[k * GPITCH + c0 + 4]);
        float b[8] = {b0.x, b0.y, b0.z, b0.w, b1.x, b1.y, b1.z, b1.w};
        #pragma unroll
        for (int i = 0; i < 8; i++)
            #pragma unroll
            for (int j = 0; j < 8; j++) acc[i][j] += a[i] * b[j];
    }

    float bb[8];
    #pragma unroll
    for (int j = 0; j < 8; j++) bb[j] = bias[c0 + j];

    const bool is_half = (y == 1 || y == 2);
    float*  outf = (y == 0) ? outq : outs;
    __half* outh = (y == 1) ? outk : outv;

    #pragma unroll
    for (int i = 0; i < 8; i++) {
        int r = row0 + r0 + i;
        if (r >= nrows) continue;
        float o[8];
        #pragma unroll
        for (int j = 0; j < 8; j++) o[j] = acc[i][j] + bb[j];
        if (is_half) {
            __half2 h4[4];
            #pragma unroll
            for (int j = 0; j < 4; j++)
                h4[j] = __floats2half2_rn(o[2 * j], o[2 * j + 1]);
            *reinterpret_cast<uint4*>(&outh[(size_t)r * 128 + c0]) =
                *reinterpret_cast<uint4*>(h4);
        } else {
            float4 o0 = make_float4(o[0], o[1], o[2], o[3]);
            float4 o1 = make_float4(o[4], o[5], o[6], o[7]);
            *reinterpret_cast<float4*>(&outf[(size_t)r * 128 + c0])     = o0;
            *reinterpret_cast<float4*>(&outf[(size_t)r * 128 + c0 + 4]) = o1;
        }
    }
}

// ==================== CSR build (once per launch) ====================
__global__ void csr_zero(int* __restrict__ deg) {
    int n = blockIdx.x * blockDim.x + threadIdx.x;
    if (n < N_NODES) deg[n] = 0;
}

__global__ __launch_bounds__(256)
void csr_count(const int* __restrict__ ei, int* __restrict__ deg) {
    int e = blockIdx.x * blockDim.x + threadIdx.x;
    if (e >= E_EDGES) return;
    atomicAdd(&deg[ei[E_EDGES + e]], 1);
}

__global__ __launch_bounds__(1024)
void csr_scan(const int* __restrict__ deg, int* __restrict__ rowstart,
              int* __restrict__ cursor)
{
    __shared__ int wsum[32];
    __shared__ int carry_sh;
    const int tid  = threadIdx.x;
    const int lane = tid & 31;
    const int wid  = tid >> 5;
    if (tid == 0) carry_sh = 0;
    __syncthreads();

    for (int base = 0; base < N_NODES; base += 1024) {
        int cv = carry_sh;
        int n  = base + tid;
        int v  = (n < N_NODES) ? deg[n] : 0;
        int x = v;
        #pragma unroll
        for (int o = 1; o < 32; o <<= 1) {
            int y = __shfl_up_sync(0xFFFFFFFFu, x, o);
            if (lane >= o) x += y;
        }
        if (lane == 31) wsum[wid] = x;
        __syncthreads();
        if (wid == 0) {
            int w = wsum[lane];
            #pragma unroll
            for (int o = 1; o < 32; o <<= 1) {
                int y = __shfl_up_sync(0xFFFFFFFFu, w, o);
                if (lane >= o) w += y;
            }
            wsum[lane] = w;
        }
        __syncthreads();
        int incl = x + (wid ? wsum[wid - 1] : 0);
        int excl = cv + incl - v;
        if (n < N_NODES) { rowstart[n] = excl; cursor[n] = excl; }
        __syncthreads();
        if (tid == 1023) carry_sh = cv + incl;
        __syncthreads();
    }
    if (tid == 0) rowstart[N_NODES] = E_EDGES;
}

__global__ __launch_bounds__(256)
void csr_scatter(const int* __restrict__ ei, int* __restrict__ cursor,
                 int* __restrict__ esrc)
{
    int e = blockIdx.x * blockDim.x + threadIdx.x;
    if (e >= E_EDGES) return;
    int dst  = ei[E_EDGES + e];
    int slot = atomicAdd(&cursor[dst], 1);
    esrc[slot] = ei[e];
}

// ==================== fused per-node attention layer (fp16 k/v) ====================
// warp per dst node: single pass; k,v rows are 256B (128 halves); lane covers 4 cols.
__global__ __launch_bounds__(256)
void gat_node(const int* __restrict__ rowstart, const int* __restrict__ esrc,
              const float* __restrict__ q, const __half* __restrict__ k,
              const __half* __restrict__ v, const float* __restrict__ skip,
              float* __restrict__ hout, int apply_elu)
{
    const int wid  = threadIdx.x >> 5;
    const int lane = threadIdx.x & 31;
    const int n    = blockIdx.x * 8 + wid;
    if (n >= N_NODES) return;

    const int beg = rowstart[n];
    const int end = rowstart[n + 1];

    float4 q4 = *reinterpret_cast<const float4*>(&q[(size_t)n * 128 + lane * 4]);
    float4 acc = make_float4(0.f, 0.f, 0.f, 0.f);
    float  den = 0.f;

    if (beg < end) {
        int src = __ldg(&esrc[beg]);
        uint2 ku = __ldg(reinterpret_cast<const uint2*>(&k[(size_t)src * 128 + lane * 4]));
        uint2 vu = __ldg(reinterpret_cast<const uint2*>(&v[(size_t)src * 128 + lane * 4]));
        for (int i = beg; i < end; i++) {
            uint2 kc = ku, vc = vu;
            if (i + 1 < end) {
                int s2 = __ldg(&esrc[i + 1]);
                ku = __ldg(reinterpret_cast<const uint2*>(&k[(size_t)s2 * 128 + lane * 4]));
                vu = __ldg(reinterpret_cast<const uint2*>(&v[(size_t)s2 * 128 + lane * 4]));
            }
            float2 k0 = __half22float2(*reinterpret_cast<__half2*>(&kc.x));
            float2 k1 = __half22float2(*reinterpret_cast<__half2*>(&kc.y));
            float p = q4.x * k0.x + q4.y * k0.y + q4.z * k1.x + q4.w * k1.y;
            #pragma unroll
            for (int off = 16; off > 0; off >>= 1)
                p += __shfl_xor_sync(0xFFFFFFFFu, p, off);
            float e = __expf(p * SCALE);
            float2 v0 = __half22float2(*reinterpret_cast<__half2*>(&vc.x));
            float2 v1 = __half22float2(*reinterpret_cast<__half2*>(&vc.y));
            den   += e;
            acc.x += e * v0.x; acc.y += e * v0.y;
            acc.z += e * v1.x; acc.w += e * v1.y;
        }
    }

    float4 s4 = *reinterpret_cast<const float4*>(&skip[(size_t)n * 128 + lane * 4]);
    float inv = (beg < end) ? (1.f / den) : 0.f;
    float4 r;
    r.x = acc.x * inv + s4.x;
    r.y = acc.y * inv + s4.y;
    r.z = acc.z * inv + s4.z;
    r.w = acc.w * inv + s4.w;
    if (apply_elu) {
        r.x = r.x > 0.f ? r.x : expm1f(r.x);
        r.y = r.y > 0.f ? r.y : expm1f(r.y);
        r.z = r.z > 0.f ? r.z : expm1f(r.z);
        r.w = r.w > 0.f ? r.w : expm1f(r.w);
    }
    *reinterpret_cast<float4*>(&hout[(size_t)n * 128 + lane * 4]) = r;
}

// ---------------- classifier: out = log_softmax(h @ fcW + fcb) ----------------
__global__ __launch_bounds__(256)
void classifier(const float* __restrict__ h, const float* __restrict__ fcW,
                const float* __restrict__ fcb, float* __restrict__ out)
{
    __shared__ float Wsh[128 * 64];
    __shared__ float hs[8][128];

    int tid = threadIdx.x;
    for (int i = tid; i < 128 * 64; i += 256) {
        int r = i >> 6, c = i & 63;
        Wsh[i] = (c < OD) ? fcW[r * OD + c] : 0.f;
    }
    __syncthreads();

    int wid  = tid >> 5;
    int lane = tid & 31;
    int n    = blockIdx.x * 8 + wid;
    if (n >= N_NODES) return;

    reinterpret_cast<float4*>(hs[wid])[lane] =
        reinterpret_cast<const float4*>(&h[(size_t)n * 128])[lane];
    __syncwarp();

    float acc0 = 0.f, acc1 = 0.f;
    #pragma unroll 8
    for (int k = 0; k < 128; k++) {
        float hv = hs[wid][k];
        acc0 += hv * Wsh[k * 64 + lane];
        acc1 += hv * Wsh[k * 64 + 32 + lane];
    }
    float val0 = acc0 + fcb[lane];
    float val1 = (lane < 8) ? (acc1 + fcb[32 + lane]) : -__int_as_float(0x7F800000);

    float vmax = fmaxf(val0, val1);
    #pragma unroll
    for (int off = 16; off > 0; off >>= 1)
        vmax = fmaxf(vmax, __shfl_xor_sync(0xFFFFFFFFu, vmax, off));

    float s = __expf(val0 - vmax) + ((lane < 8) ? __expf(val1 - vmax) : 0.f);
    #pragma unroll
    for (int off = 16; off > 0; off >>= 1)
        s += __shfl_xor_sync(0xFFFFFFFFu, s, off);

    float lse = vmax + logf(s);
    out[(size_t)n * OD + lane] = val0 - lse;
    if (lane < 8) out[(size_t)n * OD + 32 + lane] = val1 - lse;
}

// ---------------- host launch ----------------
extern "C" void kernel_launch(void* const* d_in, const int* in_sizes, int n_in,
                              void* d_out, int out_size)
{
    const float* x     = (const float*)d_in[0];
    const int*   ei    = (const int*)  d_in[1];
    const float* lin_W = (const float*)d_in[2];
    const float* lin_b = (const float*)d_in[3];
    const float* Wq    = (const float*)d_in[4];
    const float* bq    = (const float*)d_in[5];
    const float* Wk    = (const float*)d_in[6];
    const float* bk    = (const float*)d_in[7];
    const float* Wv    = (const float*)d_in[8];
    const float* bv    = (const float*)d_in[9];
    const float* Wsk   = (const float*)d_in[10];
    const float* bsk   = (const float*)d_in[11];
    const float* fcW   = (const float*)d_in[12];
    const float* fcb   = (const float*)d_in[13];
    float* out = (float*)d_out;

    float *h, *q, *s;
    __half *k, *v;
    int *deg, *rowstart, *cursor, *esrc;
    cudaGetSymbolAddress((void**)&h,        g_h);
    cudaGetSymbolAddress((void**)&q,        g_q);
    cudaGetSymbolAddress((void**)&k,        g_k);
    cudaGetSymbolAddress((void**)&v,        g_v);
    cudaGetSymbolAddress((void**)&s,        g_s);
    cudaGetSymbolAddress((void**)&deg,      g_deg);
    cudaGetSymbolAddress((void**)&rowstart, g_rowstart);
    cudaGetSymbolAddress((void**)&cursor,   g_cursor);
    cudaGetSymbolAddress((void**)&esrc,     g_esrc);

    cudaFuncSetAttribute(gemm_layer, cudaFuncAttributeMaxDynamicSharedMemorySize, GEMM_SMEM);

    const int GB  = (N_NODES + 127) / 128;
    const int NB  = (N_NODES + 255) / 256;
    const int ETB = (E_EDGES + 255) / 256;
    const int WNB = (N_NODES + 7) / 8;

    // ---- CSR build ----
    csr_zero<<<NB, 256>>>(deg);
    csr_count<<<ETB, 256>>>(ei, deg);
    csr_scan<<<1, 1024>>>(deg, rowstart, cursor);
    csr_scatter<<<ETB, 256>>>(ei, cursor, esrc);

    // ---- input projection (single GEMM via y=0 path) ----
    gemm_layer<<<dim3(GB, 1), 256, GEMM_SMEM>>>(
        x, lin_W, lin_W, lin_W, lin_W, lin_b, lin_b, lin_b, lin_b,
        h, k, v, h, N_NODES);

    for (int l = 0; l < NLAYERS; l++) {
        const float* Wq_l = Wq  + (size_t)l * HD * HD;
        const float* Wk_l = Wk  + (size_t)l * HD * HD;
        const float* Wv_l = Wv  + (size_t)l * HD * HD;
        const float* Ws_l = Wsk + (size_t)l * HD * HD;
        const float* bq_l = bq  + (size_t)l * HD;
        const float* bk_l = bk  + (size_t)l * HD;
        const float* bv_l = bv  + (size_t)l * HD;
        const float* bs_l = bsk + (size_t)l * HD;

        // 4 GEMMs in one launch (wave-quantization amortized)
        gemm_layer<<<dim3(GB, 4), 256, GEMM_SMEM>>>(
            h, Wq_l, Wk_l, Wv_l, Ws_l, bq_l, bk_l, bv_l, bs_l,
            q, k, v, s, N_NODES);

        gat_node<<<WNB, 256>>>(rowstart, esrc, q, k, v, s, h,
                               (l < NLAYERS - 1) ? 1 : 0);
    }

    classifier<<<WNB, 256>>>(h, fcW, fcb, out);
}

// round 9
// speedup vs baseline: 1.4769x; 1.0551x over previous
#include <cuda_runtime.h>
#include <cuda_fp16.h>
#include <math.h>
#include <cstdint>

#define N_NODES 100000
#define E_EDGES 1600000
#define HD 128
#define OD 40
#define NLAYERS 4
#define SCALE 0.08838834764831845f  // 1/sqrt(128)

// ---------------- device scratch (no allocations allowed) ----------------
__device__ float  g_h[(size_t)N_NODES * HD];
__device__ float  g_q[(size_t)N_NODES * HD];      // qm = h @ M
__device__ float  g_s[(size_t)N_NODES * HD];      // skip GEMM output
__device__ __half g_kv0[(size_t)N_NODES * 256];   // [n][0:128]=h16, [n][128:256]=v16
__device__ __half g_kv1[(size_t)N_NODES * 256];
__device__ float  g_beta[N_NODES];
__device__ float  g_M[HD * HD];                   // SCALE * Wq @ Wk^T
__device__ float  g_w[HD];                        // SCALE * Wk @ bq
__device__ float  g_zero[HD];                     // stays zero (bias for qm GEMM)
__device__ int    g_deg[N_NODES];
__device__ int    g_rowstart[N_NODES + 1];
__device__ int    g_cursor[N_NODES];
__device__ int    g_esrc[E_EDGES];

// ==================== per-layer bilinear prep ====================
// M[a,b] = SCALE * sum_c Wq[a,c]*Wk[b,c];  w[b] = SCALE * sum_c Wk[b,c]*bq[c].
// 16 blocks, each handles 8 b-columns; Wq staged transposed in smem.
#define PREP_SMEM ((128 * 132 + 8 * 132 + 128) * 4)

__global__ __launch_bounds__(256)
void prep_M(const float* __restrict__ Wq, const float* __restrict__ Wk,
            const float* __restrict__ bq)
{
    extern __shared__ float ps[];
    float* Wqs = ps;                    // [c*132 + a]
    float* Wks = ps + 128 * 132;        // [b_local*132 + c]
    float* bqs = Wks + 8 * 132;

    const int tid = threadIdx.x;
    const int b0  = blockIdx.x * 8;

    // stage Wq transposed: Wqs[c][a] = Wq[a][c]
    for (int idx = tid; idx < 128 * 32; idx += 256) {
        int a  = idx >> 5;
        int c4 = (idx & 31) * 4;
        float4 w4 = *reinterpret_cast<const float4*>(&Wq[a * 128 + c4]);
        Wqs[(c4 + 0) * 132 + a] = w4.x;
        Wqs[(c4 + 1) * 132 + a] = w4.y;
        Wqs[(c4 + 2) * 132 + a] = w4.z;
        Wqs[(c4 + 3) * 132 + a] = w4.w;
    }
    // stage Wk rows b0..b0+7
    for (int i = tid; i < 8 * 32; i += 256) {
        int b  = i >> 5;
        int c4 = (i & 31) * 4;
        *reinterpret_cast<float4*>(&Wks[b * 132 + c4]) =
            *reinterpret_cast<const float4*>(&Wk[(b0 + b) * 128 + c4]);
    }
    if (tid < 128) bqs[tid] = bq[tid];
    __syncthreads();

    const int a  = tid & 127;
    const int bh = tid >> 7;            // 0 or 1 -> b-quad
    float acc[4] = {0.f, 0.f, 0.f, 0.f};
    #pragma unroll 4
    for (int c = 0; c < 128; c++) {
        float wq = Wqs[c * 132 + a];
        #pragma unroll
        for (int j = 0; j < 4; j++)
            acc[j] += wq * Wks[(bh * 4 + j) * 132 + c];
    }
    #pragma unroll
    for (int j = 0; j < 4; j++)
        g_M[a * 128 + b0 + bh * 4 + j] = acc[j] * SCALE;

    if (tid < 8) {
        float s = 0.f;
        for (int c = 0; c < 128; c++) s += Wks[tid * 132 + c] * bqs[c];
        g_w[b0 + tid] = s * SCALE;
    }
}

// ==================== per-node beta: beta[n] = h_n . g_w ====================
__global__ __launch_bounds__(256)
void beta_k(const float* __restrict__ h, float* __restrict__ beta)
{
    const int wid  = threadIdx.x >> 5;
    const int lane = threadIdx.x & 31;
    const int n    = blockIdx.x * 8 + wid;
    if (n >= N_NODES) return;
    float4 h4 = *reinterpret_cast<const float4*>(&h[(size_t)n * 128 + lane * 4]);
    float4 w4 = *reinterpret_cast<const float4*>(&g_w[lane * 4]);
    float p = h4.x * w4.x + h4.y * w4.y + h4.z * w4.z + h4.w * w4.w;
    #pragma unroll
    for (int off = 16; off > 0; off >>= 1)
        p += __shfl_xor_sync(0xFFFFFFFFu, p, off);
    if (lane == 0) beta[n] = p;
}

// ==================== fused per-layer GEMM (3 outputs) ====================
// y=0: qm = A@W0 (+b0) fp32 [+ optional dual fp16 h into kv h-part, for input proj]
// y=1: v  = A@W1 (+b1) fp16 -> kv[n][128:256]
// y=2: s  = A@W2 (+b2) fp32
// Scalar FFMA inner loop: verified at the fp32 roofline — do not touch.
#define GPITCH 132
#define GEMM_SMEM (2 * 128 * GPITCH * 4)

__global__ __launch_bounds__(256, 1)
void gemm3(const float* __restrict__ A,
           const float* __restrict__ W0, const float* __restrict__ W1,
           const float* __restrict__ W2,
           const float* __restrict__ b0, const float* __restrict__ b1,
           const float* __restrict__ b2,
           float* __restrict__ out0, __half* __restrict__ kvv,
           float* __restrict__ out2, __half* __restrict__ kv_h_dual,
           int nrows)
{
    extern __shared__ float sm[];
    float* As = sm;
    float* Ws = sm + 128 * GPITCH;

    const int y = blockIdx.y;
    const float* W    = (y == 0) ? W0 : (y == 1) ? W1 : W2;
    const float* bias = (y == 0) ? b0 : (y == 1) ? b1 : b2;

    const int tid  = threadIdx.x;
    const int row0 = blockIdx.x * 128;

    #pragma unroll
    for (int c = 0; c < 16; c++) {
        int idx = c * 256 + tid;
        int r   = idx >> 5;
        int c4  = (idx & 31) * 4;
        float4 w4 = *reinterpret_cast<const float4*>(&W[r * 128 + c4]);
        *reinterpret_cast<float4*>(&Ws[r * GPITCH + c4]) = w4;
        int ar = row0 + r;
        float4 a4 = make_float4(0.f, 0.f, 0.f, 0.f);
        if (ar < nrows) a4 = *reinterpret_cast<const float4*>(&A[(size_t)ar * 128 + c4]);
        *reinterpret_cast<float4*>(&As[r * GPITCH + c4]) = a4;
    }
    __syncthreads();

    const int tx = tid & 15, ty = tid >> 4;
    const int r0 = ty * 8, c0 = tx * 8;

    float acc[8][8];
    #pragma unroll
    for (int i = 0; i < 8; i++)
        #pragma unroll
        for (int j = 0; j < 8; j++) acc[i][j] = 0.f;

    #pragma unroll 8
    for (int k = 0; k < 128; k++) {
        float a[8];
        #pragma unroll
        for (int i = 0; i < 8; i++) a[i] = As[(r0 + i) * GPITCH + k];
        float4 bb0 = *reinterpret_cast<const float4*>(&Ws[k * GPITCH + c0]);
        float4 bb1 = *reinterpret_cast<const float4*>(&Ws[k * GPITCH + c0 + 4]);
        float b[8] = {bb0.x, bb0.y, bb0.z, bb0.w, bb1.x, bb1.y, bb1.z, bb1.w};
        #pragma unroll
        for (int i = 0; i < 8; i++)
            #pragma unroll
            for (int j = 0; j < 8; j++) acc[i][j] += a[i] * b[j];
    }

    float bb[8];
    #pragma unroll
    for (int j = 0; j < 8; j++) bb[j] = bias[c0 + j];

    #pragma unroll
    for (int i = 0; i < 8; i++) {
        int r = row0 + r0 + i;
        if (r >= nrows) continue;
        float o[8];
        #pragma unroll
        for (int j = 0; j < 8; j++) o[j] = acc[i][j] + bb[j];
        if (y == 1) {
            __half2 h4[4];
            #pragma unroll
            for (int j = 0; j < 4; j++)
                h4[j] = __floats2half2_rn(o[2 * j], o[2 * j + 1]);
            *reinterpret_cast<uint4*>(&kvv[(size_t)r * 256 + 128 + c0]) =
                *reinterpret_cast<uint4*>(h4);
        } else {
            float* outf = (y == 0) ? out0 : out2;
            float4 o0 = make_float4(o[0], o[1], o[2], o[3]);
            float4 o1 = make_float4(o[4], o[5], o[6], o[7]);
            *reinterpret_cast<float4*>(&outf[(size_t)r * 128 + c0])     = o0;
            *reinterpret_cast<float4*>(&outf[(size_t)r * 128 + c0 + 4]) = o1;
            if (y == 0 && kv_h_dual) {
                __half2 h4[4];
                #pragma unroll
                for (int j = 0; j < 4; j++)
                    h4[j] = __floats2half2_rn(o[2 * j], o[2 * j + 1]);
                *reinterpret_cast<uint4*>(&kv_h_dual[(size_t)r * 256 + c0]) =
                    *reinterpret_cast<uint4*>(h4);
            }
        }
    }
}

// ==================== CSR build (once per launch) ====================
__global__ void csr_zero(int* __restrict__ deg) {
    int n = blockIdx.x * blockDim.x + threadIdx.x;
    if (n < N_NODES) deg[n] = 0;
}

__global__ __launch_bounds__(256)
void csr_count(const int* __restrict__ ei, int* __restrict__ deg) {
    int e = blockIdx.x * blockDim.x + threadIdx.x;
    if (e >= E_EDGES) return;
    atomicAdd(&deg[ei[E_EDGES + e]], 1);
}

__global__ __launch_bounds__(1024)
void csr_scan(const int* __restrict__ deg, int* __restrict__ rowstart,
              int* __restrict__ cursor)
{
    __shared__ int wsum[32];
    __shared__ int carry_sh;
    const int tid  = threadIdx.x;
    const int lane = tid & 31;
    const int wid  = tid >> 5;
    if (tid == 0) carry_sh = 0;
    __syncthreads();

    for (int base = 0; base < N_NODES; base += 1024) {
        int cv = carry_sh;
        int n  = base + tid;
        int v  = (n < N_NODES) ? deg[n] : 0;
        int x = v;
        #pragma unroll
        for (int o = 1; o < 32; o <<= 1) {
            int yv = __shfl_up_sync(0xFFFFFFFFu, x, o);
            if (lane >= o) x += yv;
        }
        if (lane == 31) wsum[wid] = x;
        __syncthreads();
        if (wid == 0) {
            int w = wsum[lane];
            #pragma unroll
            for (int o = 1; o < 32; o <<= 1) {
                int yv = __shfl_up_sync(0xFFFFFFFFu, w, o);
                if (lane >= o) w += yv;
            }
            wsum[lane] = w;
        }
        __syncthreads();
        int incl = x + (wid ? wsum[wid - 1] : 0);
        int excl = cv + incl - v;
        if (n < N_NODES) { rowstart[n] = excl; cursor[n] = excl; }
        __syncthreads();
        if (tid == 1023) carry_sh = cv + incl;
        __syncthreads();
    }
    if (tid == 0) rowstart[N_NODES] = E_EDGES;
}

__global__ __launch_bounds__(256)
void csr_scatter(const int* __restrict__ ei, int* __restrict__ cursor,
                 int* __restrict__ esrc)
{
    int e = blockIdx.x * blockDim.x + threadIdx.x;
    if (e >= E_EDGES) return;
    int dst  = ei[E_EDGES + e];
    int slot = atomicAdd(&cursor[dst], 1);
    esrc[slot] = ei[e];
}

// ==================== fused per-node attention layer ====================
// logit_e = qm[dst] . h16[src] + beta[src]   (segment-constant terms cancel in softmax)
// kv_in:  [src][0:128]=h16(layer l), [src][128:256]=v16(layer l)  -- read
// kv_out: [n][0:128] = h16(layer l+1)                             -- written iff write_h16
__global__ __launch_bounds__(256)
void gat_node(const int* __restrict__ rowstart, const int* __restrict__ esrc,
              const float* __restrict__ qm, const __half* __restrict__ kv_in,
              const float* __restrict__ beta, const float* __restrict__ skip,
              float* __restrict__ hout, __half* __restrict__ kv_out,
              int write_h16)
{
    const int wid  = threadIdx.x >> 5;
    const int lane = threadIdx.x & 31;
    const int n    = blockIdx.x * 8 + wid;
    if (n >= N_NODES) return;

    const int beg = rowstart[n];
    const int end = rowstart[n + 1];

    float4 q4 = *reinterpret_cast<const float4*>(&qm[(size_t)n * 128 + lane * 4]);
    float4 acc = make_float4(0.f, 0.f, 0.f, 0.f);
    float  den = 0.f;

    if (beg < end) {
        int src = __ldg(&esrc[beg]);
        uint2 ku = __ldg(reinterpret_cast<const uint2*>(&kv_in[(size_t)src * 256 + lane * 4]));
        uint2 vu = __ldg(reinterpret_cast<const uint2*>(&kv_in[(size_t)src * 256 + 128 + lane * 4]));
        float bt = __ldg(&beta[src]);
        for (int i = beg; i < end; i++) {
            uint2 kc = ku, vc = vu;
            float bc = bt;
            if (i + 1 < end) {
                int s2 = __ldg(&esrc[i + 1]);
                ku = __ldg(reinterpret_cast<const uint2*>(&kv_in[(size_t)s2 * 256 + lane * 4]));
                vu = __ldg(reinterpret_cast<const uint2*>(&kv_in[(size_t)s2 * 256 + 128 + lane * 4]));
                bt = __ldg(&beta[s2]);
            }
            float2 k0 = __half22float2(*reinterpret_cast<__half2*>(&kc.x));
            float2 k1 = __half22float2(*reinterpret_cast<__half2*>(&kc.y));
            float p = q4.x * k0.x + q4.y * k0.y + q4.z * k1.x + q4.w * k1.y;
            #pragma unroll
            for (int off = 16; off > 0; off >>= 1)
                p += __shfl_xor_sync(0xFFFFFFFFu, p, off);
            float e = __expf(p + bc);
            float2 v0 = __half22float2(*reinterpret_cast<__half2*>(&vc.x));
            float2 v1 = __half22float2(*reinterpret_cast<__half2*>(&vc.y));
            den   += e;
            acc.x += e * v0.x; acc.y += e * v0.y;
            acc.z += e * v1.x; acc.w += e * v1.y;
        }
    }

    float4 s4 = *reinterpret_cast<const float4*>(&skip[(size_t)n * 128 + lane * 4]);
    float inv = (beg < end) ? (1.f / den) : 0.f;
    float4 r;
    r.x = acc.x * inv + s4.x;
    r.y = acc.y * inv + s4.y;
    r.z = acc.z * inv + s4.z;
    r.w = acc.w * inv + s4.w;
    if (write_h16) {   // all but last layer also apply ELU
        r.x = r.x > 0.f ? r.x : expm1f(r.x);
        r.y = r.y > 0.f ? r.y : expm1f(r.y);
        r.z = r.z > 0.f ? r.z : expm1f(r.z);
        r.w = r.w > 0.f ? r.w : expm1f(r.w);
        __half2 h0 = __floats2half2_rn(r.x, r.y);
        __half2 h1 = __floats2half2_rn(r.z, r.w);
        uint2 hv;
        hv.x = *reinterpret_cast<uint32_t*>(&h0);
        hv.y = *reinterpret_cast<uint32_t*>(&h1);
        *reinterpret_cast<uint2*>(&kv_out[(size_t)n * 256 + lane * 4]) = hv;
    }
    *reinterpret_cast<float4*>(&hout[(size_t)n * 128 + lane * 4]) = r;
}

// ---------------- classifier: out = log_softmax(h @ fcW + fcb) ----------------
__global__ __launch_bounds__(256)
void classifier(const float* __restrict__ h, const float* __restrict__ fcW,
                const float* __restrict__ fcb, float* __restrict__ out)
{
    __shared__ float Wsh[128 * 64];
    __shared__ float hs[8][128];

    int tid = threadIdx.x;
    for (int i = tid; i < 128 * 64; i += 256) {
        int r = i >> 6, c = i & 63;
        Wsh[i] = (c < OD) ? fcW[r * OD + c] : 0.f;
    }
    __syncthreads();

    int wid  = tid >> 5;
    int lane = tid & 31;
    int n    = blockIdx.x * 8 + wid;
    if (n >= N_NODES) return;

    reinterpret_cast<float4*>(hs[wid])[lane] =
        reinterpret_cast<const float4*>(&h[(size_t)n * 128])[lane];
    __syncwarp();

    float acc0 = 0.f, acc1 = 0.f;
    #pragma unroll 8
    for (int k = 0; k < 128; k++) {
        float hv = hs[wid][k];
        acc0 += hv * Wsh[k * 64 + lane];
        acc1 += hv * Wsh[k * 64 + 32 + lane];
    }
    float val0 = acc0 + fcb[lane];
    float val1 = (lane < 8) ? (acc1 + fcb[32 + lane]) : -__int_as_float(0x7F800000);

    float vmax = fmaxf(val0, val1);
    #pragma unroll
    for (int off = 16; off > 0; off >>= 1)
        vmax = fmaxf(vmax, __shfl_xor_sync(0xFFFFFFFFu, vmax, off));

    float s = __expf(val0 - vmax) + ((lane < 8) ? __expf(val1 - vmax) : 0.f);
    #pragma unroll
    for (int off = 16; off > 0; off >>= 1)
        s += __shfl_xor_sync(0xFFFFFFFFu, s, off);

    float lse = vmax + logf(s);
    out[(size_t)n * OD + lane] = val0 - lse;
    if (lane < 8) out[(size_t)n * OD + 32 + lane] = val1 - lse;
}

// ---------------- host launch ----------------
extern "C" void kernel_launch(void* const* d_in, const int* in_sizes, int n_in,
                              void* d_out, int out_size)
{
    const float* x     = (const float*)d_in[0];
    const int*   ei    = (const int*)  d_in[1];
    const float* lin_W = (const float*)d_in[2];
    const float* lin_b = (const float*)d_in[3];
    const float* Wq    = (const float*)d_in[4];
    const float* bq    = (const float*)d_in[5];
    const float* Wk    = (const float*)d_in[6];
    const float* bk    = (const float*)d_in[7];   // cancels in softmax; unused
    const float* Wv    = (const float*)d_in[8];
    const float* bv    = (const float*)d_in[9];
    const float* Wsk   = (const float*)d_in[10];
    const float* bsk   = (const float*)d_in[11];
    const float* fcW   = (const float*)d_in[12];
    const float* fcb   = (const float*)d_in[13];
    float* out = (float*)d_out;
    (void)bk;

    float *h, *qm, *s, *beta, *Mp, *zerop;
    __half *kv0, *kv1;
    int *deg, *rowstart, *cursor, *esrc;
    cudaGetSymbolAddress((void**)&h,        g_h);
    cudaGetSymbolAddress((void**)&qm,       g_q);
    cudaGetSymbolAddress((void**)&s,        g_s);
    cudaGetSymbolAddress((void**)&beta,     g_beta);
    cudaGetSymbolAddress((void**)&Mp,       g_M);
    cudaGetSymbolAddress((void**)&zerop,    g_zero);
    cudaGetSymbolAddress((void**)&kv0,      g_kv0);
    cudaGetSymbolAddress((void**)&kv1,      g_kv1);
    cudaGetSymbolAddress((void**)&deg,      g_deg);
    cudaGetSymbolAddress((void**)&rowstart, g_rowstart);
    cudaGetSymbolAddress((void**)&cursor,   g_cursor);
    cudaGetSymbolAddress((void**)&esrc,     g_esrc);

    cudaFuncSetAttribute(gemm3,  cudaFuncAttributeMaxDynamicSharedMemorySize, GEMM_SMEM);
    cudaFuncSetAttribute(prep_M, cudaFuncAttributeMaxDynamicSharedMemorySize, PREP_SMEM);

    const int GB  = (N_NODES + 127) / 128;
    const int NB  = (N_NODES + 255) / 256;
    const int ETB = (E_EDGES + 255) / 256;
    const int WNB = (N_NODES + 7) / 8;

    // ---- CSR build ----
    csr_zero<<<NB, 256>>>(deg);
    csr_count<<<ETB, 256>>>(ei, deg);
    csr_scan<<<1, 1024>>>(deg, rowstart, cursor);
    csr_scatter<<<ETB, 256>>>(ei, cursor, esrc);

    // ---- input projection: h = x@lin_W + lin_b (fp32 + dual fp16 into kv0 h-part) ----
    gemm3<<<dim3(GB, 1), 256, GEMM_SMEM>>>(
        x, lin_W, lin_W, lin_W, lin_b, lin_b, lin_b,
        h, kv0, h, kv0, N_NODES);

    for (int l = 0; l < NLAYERS; l++) {
        const float* Wq_l = Wq  + (size_t)l * HD * HD;
        const float* Wk_l = Wk  + (size_t)l * HD * HD;
        const float* Wv_l = Wv  + (size_t)l * HD * HD;
        const float* Ws_l = Wsk + (size_t)l * HD * HD;
        const float* bq_l = bq  + (size_t)l * HD;
        const float* bv_l = bv  + (size_t)l * HD;
        const float* bs_l = bsk + (size_t)l * HD;

        __half* kv_cur  = (l & 1) ? kv1 : kv0;
        __half* kv_next = (l & 1) ? kv0 : kv1;

        prep_M<<<16, 256, PREP_SMEM>>>(Wq_l, Wk_l, bq_l);

        // 3 GEMMs in one launch: qm = h@M, v16 -> kv_cur, s = h@Ws
        gemm3<<<dim3(GB, 3), 256, GEMM_SMEM>>>(
            h, Mp, Wv_l, Ws_l, zerop, bv_l, bs_l,
            qm, kv_cur, s, nullptr, N_NODES);

        beta_k<<<WNB, 256>>>(h, beta);

        gat_node<<<WNB, 256>>>(rowstart, esrc, qm, kv_cur, beta, s, h, kv_next,
                               (l < NLAYERS - 1) ? 1 : 0);
    }

    classifier<<<WNB, 256>>>(h, fcW, fcb, out);
}

// round 10
// speedup vs baseline: 1.4970x; 1.0136x over previous
#include <cuda_runtime.h>
#include <cuda_fp16.h>
#include <math.h>
#include <cstdint>

#define N_NODES 100000
#define E_EDGES 1600000
#define HD 128
#define OD 40
#define NLAYERS 4
#define SCALE 0.08838834764831845f  // 1/sqrt(128)

// ---------------- device scratch (no allocations allowed) ----------------
__device__ float  g_h[(size_t)N_NODES * HD];
__device__ float  g_q[(size_t)N_NODES * HD];      // qm = h @ M
__device__ float  g_s[(size_t)N_NODES * HD];      // skip GEMM output
__device__ __half g_kv0[(size_t)N_NODES * 256];   // [n][0:128]=h16, [n][128:256]=v16
__device__ __half g_kv1[(size_t)N_NODES * 256];
__device__ float  g_beta[N_NODES];
__device__ float  g_M[NLAYERS * HD * HD];         // SCALE * Wq @ Wk^T, per layer
__device__ float  g_w[NLAYERS * HD];              // SCALE * Wk @ bq, per layer
__device__ float  g_zero[HD];                     // stays zero (bias for qm GEMM)
__device__ int    g_deg[N_NODES];
__device__ int    g_rowstart[N_NODES + 1];
__device__ int    g_cursor[N_NODES];
__device__ int    g_esrc[E_EDGES];

// ==================== bilinear prep for ALL layers (weights-only) ====================
// M_l[a,b] = SCALE * sum_c Wq_l[a,c]*Wk_l[b,c];  w_l[b] = SCALE * sum_c Wk_l[b,c]*bq_l[c].
// 64 blocks: blockIdx>>4 = layer, (blockIdx&15)*8 = b-chunk.
#define PREP_SMEM ((128 * 132 + 8 * 132 + 128) * 4)

__global__ __launch_bounds__(256)
void prep_all(const float* __restrict__ Wq, const float* __restrict__ Wk,
              const float* __restrict__ bq)
{
    extern __shared__ float ps[];
    float* Wqs = ps;                    // [c*132 + a]
    float* Wks = ps + 128 * 132;        // [b_local*132 + c]
    float* bqs = Wks + 8 * 132;

    const int tid   = threadIdx.x;
    const int layer = blockIdx.x >> 4;
    const int b0    = (blockIdx.x & 15) * 8;
    const float* Wq_l = Wq + (size_t)layer * HD * HD;
    const float* Wk_l = Wk + (size_t)layer * HD * HD;
    const float* bq_l = bq + (size_t)layer * HD;

    // stage Wq transposed: Wqs[c][a] = Wq[a][c]
    for (int idx = tid; idx < 128 * 32; idx += 256) {
        int a  = idx >> 5;
        int c4 = (idx & 31) * 4;
        float4 w4 = *reinterpret_cast<const float4*>(&Wq_l[a * 128 + c4]);
        Wqs[(c4 + 0) * 132 + a] = w4.x;
        Wqs[(c4 + 1) * 132 + a] = w4.y;
        Wqs[(c4 + 2) * 132 + a] = w4.z;
        Wqs[(c4 + 3) * 132 + a] = w4.w;
    }
    for (int i = tid; i < 8 * 32; i += 256) {
        int b  = i >> 5;
        int c4 = (i & 31) * 4;
        *reinterpret_cast<float4*>(&Wks[b * 132 + c4]) =
            *reinterpret_cast<const float4*>(&Wk_l[(b0 + b) * 128 + c4]);
    }
    if (tid < 128) bqs[tid] = bq_l[tid];
    __syncthreads();

    const int a  = tid & 127;
    const int bh = tid >> 7;            // 0 or 1 -> b-quad
    float acc[4] = {0.f, 0.f, 0.f, 0.f};
    #pragma unroll 4
    for (int c = 0; c < 128; c++) {
        float wq = Wqs[c * 132 + a];
        #pragma unroll
        for (int j = 0; j < 4; j++)
            acc[j] += wq * Wks[(bh * 4 + j) * 132 + c];
    }
    #pragma unroll
    for (int j = 0; j < 4; j++)
        g_M[(size_t)layer * HD * HD + a * 128 + b0 + bh * 4 + j] = acc[j] * SCALE;

    if (tid < 8) {
        float s = 0.f;
        for (int c = 0; c < 128; c++) s += Wks[tid * 132 + c] * bqs[c];
        g_w[layer * HD + b0 + tid] = s * SCALE;
    }
}

// ==================== fused per-layer GEMM (3 outputs + beta) ====================
// y=0: qm = A@W0 (+b0) fp32; also beta[r]=A_r.wvec; optional dual fp16 into kv h-part
// y=1: v  = A@W1 (+b1) fp16 -> kv[n][128:256]
// y=2: s  = A@W2 (+b2) fp32
// As stored TRANSPOSED (k-major) so A-fragments are broadcast LDS.128, not
// bank-conflicted scalar LDS (the 4224B row stride put both ty-rows in bank 0).
#define GPITCH 132
#define GEMM_SMEM (2 * 128 * GPITCH * 4)

__global__ __launch_bounds__(256, 1)
void gemm3(const float* __restrict__ A,
           const float* __restrict__ W0, const float* __restrict__ W1,
           const float* __restrict__ W2,
           const float* __restrict__ b0, const float* __restrict__ b1,
           const float* __restrict__ b2,
           float* __restrict__ out0, __half* __restrict__ kvv,
           float* __restrict__ out2, __half* __restrict__ kv_h_dual,
           const float* __restrict__ wvec, float* __restrict__ betap,
           int nrows)
{
    extern __shared__ float sm[];
    float* AsT = sm;                   // [k*GPITCH + m], k=0..127, m=0..127
    float* Ws  = sm + 128 * GPITCH;    // [k*GPITCH + n]
    __shared__ float wsh[128];

    const int y = blockIdx.y;
    const float* W    = (y == 0) ? W0 : (y == 1) ? W1 : W2;
    const float* bias = (y == 0) ? b0 : (y == 1) ? b1 : b2;

    const int tid  = threadIdx.x;
    const int row0 = blockIdx.x * 128;

    // ---- stage A transposed: conflict-free STS (r contiguous per warp) ----
    #pragma unroll
    for (int c = 0; c < 16; c++) {
        int idx = c * 256 + tid;
        int r   = idx & 127;           // tile row
        int kq  = (idx >> 7) * 4;      // k quad
        int ar  = row0 + r;
        float4 a4 = make_float4(0.f, 0.f, 0.f, 0.f);
        if (ar < nrows) a4 = *reinterpret_cast<const float4*>(&A[(size_t)ar * 128 + kq]);
        AsT[(kq + 0) * GPITCH + r] = a4.x;
        AsT[(kq + 1) * GPITCH + r] = a4.y;
        AsT[(kq + 2) * GPITCH + r] = a4.z;
        AsT[(kq + 3) * GPITCH + r] = a4.w;
    }
    // ---- stage W (already k-major): coalesced ----
    #pragma unroll
    for (int c = 0; c < 16; c++) {
        int idx = c * 256 + tid;
        int r   = idx >> 5;
        int c4  = (idx & 31) * 4;
        *reinterpret_cast<float4*>(&Ws[r * GPITCH + c4]) =
            *reinterpret_cast<const float4*>(&W[r * 128 + c4]);
    }
    if (tid < 128) wsh[tid] = wvec ? wvec[tid] : 0.f;
    __syncthreads();

    const int tx = tid & 15, ty = tid >> 4;
    const int r0 = ty * 8, c0 = tx * 8;

    float acc[8][8];
    #pragma unroll
    for (int i = 0; i < 8; i++)
        #pragma unroll
        for (int j = 0; j < 8; j++) acc[i][j] = 0.f;

    #pragma unroll 8
    for (int k = 0; k < 128; k++) {
        float4 a0 = *reinterpret_cast<const float4*>(&AsT[k * GPITCH + r0]);
        float4 a1 = *reinterpret_cast<const float4*>(&AsT[k * GPITCH + r0 + 4]);
        float a[8] = {a0.x, a0.y, a0.z, a0.w, a1.x, a1.y, a1.z, a1.w};
        float4 bb0 = *reinterpret_cast<const float4*>(&Ws[k * GPITCH + c0]);
        float4 bb1 = *reinterpret_cast<const float4*>(&Ws[k * GPITCH + c0 + 4]);
        float b[8] = {bb0.x, bb0.y, bb0.z, bb0.w, bb1.x, bb1.y, bb1.z, bb1.w};
        #pragma unroll
        for (int i = 0; i < 8; i++)
            #pragma unroll
            for (int j = 0; j < 8; j++) acc[i][j] += a[i] * b[j];
    }

    // ---- beta for this row-block (y=0 only): beta[r] = A_r . wvec ----
    if (y == 0 && betap != nullptr && tid < 128) {
        int rr = row0 + tid;
        if (rr < nrows) {
            float bsum = 0.f;
            #pragma unroll 8
            for (int b = 0; b < 128; b++) bsum += AsT[b * GPITCH + tid] * wsh[b];
            betap[rr] = bsum;
        }
    }

    float bb[8];
    #pragma unroll
    for (int j = 0; j < 8; j++) bb[j] = bias[c0 + j];

    #pragma unroll
    for (int i = 0; i < 8; i++) {
        int r = row0 + r0 + i;
        if (r >= nrows) continue;
        float o[8];
        #pragma unroll
        for (int j = 0; j < 8; j++) o[j] = acc[i][j] + bb[j];
        if (y == 1) {
            __half2 h4[4];
            #pragma unroll
            for (int j = 0; j < 4; j++)
                h4[j] = __floats2half2_rn(o[2 * j], o[2 * j + 1]);
            *reinterpret_cast<uint4*>(&kvv[(size_t)r * 256 + 128 + c0]) =
                *reinterpret_cast<uint4*>(h4);
        } else {
            float* outf = (y == 0) ? out0 : out2;
            float4 o0 = make_float4(o[0], o[1], o[2], o[3]);
            float4 o1 = make_float4(o[4], o[5], o[6], o[7]);
            *reinterpret_cast<float4*>(&outf[(size_t)r * 128 + c0])     = o0;
            *reinterpret_cast<float4*>(&outf[(size_t)r * 128 + c0 + 4]) = o1;
            if (y == 0 && kv_h_dual) {
                __half2 h4[4];
                #pragma unroll
                for (int j = 0; j < 4; j++)
                    h4[j] = __floats2half2_rn(o[2 * j], o[2 * j + 1]);
                *reinterpret_cast<uint4*>(&kv_h_dual[(size_t)r * 256 + c0]) =
                    *reinterpret_cast<uint4*>(h4);
            }
        }
    }
}

// ==================== CSR build (once per launch) ====================
__global__ void csr_zero(int* __restrict__ deg) {
    int n = blockIdx.x * blockDim.x + threadIdx.x;
    if (n < N_NODES) deg[n] = 0;
}

__global__ __launch_bounds__(256)
void csr_count(const int* __restrict__ ei, int* __restrict__ deg) {
    int e = blockIdx.x * blockDim.x + threadIdx.x;
    if (e >= E_EDGES) return;
    atomicAdd(&deg[ei[E_EDGES + e]], 1);
}

__global__ __launch_bounds__(1024)
void csr_scan(const int* __restrict__ deg, int* __restrict__ rowstart,
              int* __restrict__ cursor)
{
    __shared__ int wsum[32];
    __shared__ int carry_sh;
    const int tid  = threadIdx.x;
    const int lane = tid & 31;
    const int wid  = tid >> 5;
    if (tid == 0) carry_sh = 0;
    __syncthreads();

    for (int base = 0; base < N_NODES; base += 1024) {
        int cv = carry_sh;
        int n  = base + tid;
        int v  = (n < N_NODES) ? deg[n] : 0;
        int x = v;
        #pragma unroll
        for (int o = 1; o < 32; o <<= 1) {
            int yv = __shfl_up_sync(0xFFFFFFFFu, x, o);
            if (lane >= o) x += yv;
        }
        if (lane == 31) wsum[wid] = x;
        __syncthreads();
        if (wid == 0) {
            int w = wsum[lane];
            #pragma unroll
            for (int o = 1; o < 32; o <<= 1) {
                int yv = __shfl_up_sync(0xFFFFFFFFu, w, o);
                if (lane >= o) w += yv;
            }
            wsum[lane] = w;
        }
        __syncthreads();
        int incl = x + (wid ? wsum[wid - 1] : 0);
        int excl = cv + incl - v;
        if (n < N_NODES) { rowstart[n] = excl; cursor[n] = excl; }
        __syncthreads();
        if (tid == 1023) carry_sh = cv + incl;
        __syncthreads();
    }
    if (tid == 0) rowstart[N_NODES] = E_EDGES;
}

__global__ __launch_bounds__(256)
void csr_scatter(const int* __restrict__ ei, int* __restrict__ cursor,
                 int* __restrict__ esrc)
{
    int e = blockIdx.x * blockDim.x + threadIdx.x;
    if (e >= E_EDGES) return;
    int dst  = ei[E_EDGES + e];
    int slot = atomicAdd(&cursor[dst], 1);
    esrc[slot] = ei[e];
}

// ==================== fused per-node attention layer ====================
// logit_e = qm[dst] . h16[src] + beta[src]   (segment-constant terms cancel in softmax)
__global__ __launch_bounds__(256)
void gat_node(const int* __restrict__ rowstart, const int* __restrict__ esrc,
              const float* __restrict__ qm, const __half* __restrict__ kv_in,
              const float* __restrict__ beta, const float* __restrict__ skip,
              float* __restrict__ hout, __half* __restrict__ kv_out,
              int write_h16)
{
    const int wid  = threadIdx.x >> 5;
    const int lane = threadIdx.x & 31;
    const int n    = blockIdx.x * 8 + wid;
    if (n >= N_NODES) return;

    const int beg = rowstart[n];
    const int end = rowstart[n + 1];

    float4 q4 = *reinterpret_cast<const float4*>(&qm[(size_t)n * 128 + lane * 4]);
    float4 acc = make_float4(0.f, 0.f, 0.f, 0.f);
    float  den = 0.f;

    if (beg < end) {
        int src = __ldg(&esrc[beg]);
        uint2 ku = __ldg(reinterpret_cast<const uint2*>(&kv_in[(size_t)src * 256 + lane * 4]));
        uint2 vu = __ldg(reinterpret_cast<const uint2*>(&kv_in[(size_t)src * 256 + 128 + lane * 4]));
        float bt = __ldg(&beta[src]);
        for (int i = beg; i < end; i++) {
            uint2 kc = ku, vc = vu;
            float bc = bt;
            if (i + 1 < end) {
                int s2 = __ldg(&esrc[i + 1]);
                ku = __ldg(reinterpret_cast<const uint2*>(&kv_in[(size_t)s2 * 256 + lane * 4]));
                vu = __ldg(reinterpret_cast<const uint2*>(&kv_in[(size_t)s2 * 256 + 128 + lane * 4]));
                bt = __ldg(&beta[s2]);
            }
            float2 k0 = __half22float2(*reinterpret_cast<__half2*>(&kc.x));
            float2 k1 = __half22float2(*reinterpret_cast<__half2*>(&kc.y));
            float p = q4.x * k0.x + q4.y * k0.y + q4.z * k1.x + q4.w * k1.y;
            #pragma unroll
            for (int off = 16; off > 0; off >>= 1)
                p += __shfl_xor_sync(0xFFFFFFFFu, p, off);
            float e = __expf(p + bc);
            float2 v0 = __half22float2(*reinterpret_cast<__half2*>(&vc.x));
            float2 v1 = __half22float2(*reinterpret_cast<__half2*>(&vc.y));
            den   += e;
            acc.x += e * v0.x; acc.y += e * v0.y;
            acc.z += e * v1.x; acc.w += e * v1.y;
        }
    }

    float4 s4 = *reinterpret_cast<const float4*>(&skip[(size_t)n * 128 + lane * 4]);
    float inv = (beg < end) ? (1.f / den) : 0.f;
    float4 r;
    r.x = acc.x * inv + s4.x;
    r.y = acc.y * inv + s4.y;
    r.z = acc.z * inv + s4.z;
    r.w = acc.w * inv + s4.w;
    if (write_h16) {   // all but last layer also apply ELU
        r.x = r.x > 0.f ? r.x : expm1f(r.x);
        r.y = r.y > 0.f ? r.y : expm1f(r.y);
        r.z = r.z > 0.f ? r.z : expm1f(r.z);
        r.w = r.w > 0.f ? r.w : expm1f(r.w);
        __half2 h0 = __floats2half2_rn(r.x, r.y);
        __half2 h1 = __floats2half2_rn(r.z, r.w);
        uint2 hv;
        hv.x = *reinterpret_cast<uint32_t*>(&h0);
        hv.y = *reinterpret_cast<uint32_t*>(&h1);
        *reinterpret_cast<uint2*>(&kv_out[(size_t)n * 256 + lane * 4]) = hv;
    }
    *reinterpret_cast<float4*>(&hout[(size_t)n * 128 + lane * 4]) = r;
}

// ---------------- classifier: out = log_softmax(h @ fcW + fcb) ----------------
__global__ __launch_bounds__(256)
void classifier(const float* __restrict__ h, const float* __restrict__ fcW,
                const float* __restrict__ fcb, float* __restrict__ out)
{
    __shared__ float Wsh[128 * 64];
    __shared__ float hs[8][128];

    int tid = threadIdx.x;
    for (int i = tid; i < 128 * 64; i += 256) {
        int r = i >> 6, c = i & 63;
        Wsh[i] = (c < OD) ? fcW[r * OD + c] : 0.f;
    }
    __syncthreads();

    int wid  = tid >> 5;
    int lane = tid & 31;
    int n    = blockIdx.x * 8 + wid;
    if (n >= N_NODES) return;

    reinterpret_cast<float4*>(hs[wid])[lane] =
        reinterpret_cast<const float4*>(&h[(size_t)n * 128])[lane];
    __syncwarp();

    float acc0 = 0.f, acc1 = 0.f;
    #pragma unroll 8
    for (int k = 0; k < 128; k++) {
        float hv = hs[wid][k];
        acc0 += hv * Wsh[k * 64 + lane];
        acc1 += hv * Wsh[k * 64 + 32 + lane];
    }
    float val0 = acc0 + fcb[lane];
    float val1 = (lane < 8) ? (acc1 + fcb[32 + lane]) : -__int_as_float(0x7F800000);

    float vmax = fmaxf(val0, val1);
    #pragma unroll
    for (int off = 16; off > 0; off >>= 1)
        vmax = fmaxf(vmax, __shfl_xor_sync(0xFFFFFFFFu, vmax, off));

    float s = __expf(val0 - vmax) + ((lane < 8) ? __expf(val1 - vmax) : 0.f);
    #pragma unroll
    for (int off = 16; off > 0; off >>= 1)
        s += __shfl_xor_sync(0xFFFFFFFFu, s, off);

    float lse = vmax + logf(s);
    out[(size_t)n * OD + lane] = val0 - lse;
    if (lane < 8) out[(size_t)n * OD + 32 + lane] = val1 - lse;
}

// ---------------- host launch ----------------
extern "C" void kernel_launch(void* const* d_in, const int* in_sizes, int n_in,
                              void* d_out, int out_size)
{
    const float* x     = (const float*)d_in[0];
    const int*   ei    = (const int*)  d_in[1];
    const float* lin_W = (const float*)d_in[2];
    const float* lin_b = (const float*)d_in[3];
    const float* Wq    = (const float*)d_in[4];
    const float* bq    = (const float*)d_in[5];
    const float* Wk    = (const float*)d_in[6];
    const float* bk    = (const float*)d_in[7];   // cancels in softmax; unused
    const float* Wv    = (const float*)d_in[8];
    const float* bv    = (const float*)d_in[9];
    const float* Wsk   = (const float*)d_in[10];
    const float* bsk   = (const float*)d_in[11];
    const float* fcW   = (const float*)d_in[12];
    const float* fcb   = (const float*)d_in[13];
    float* out = (float*)d_out;
    (void)bk;

    float *h, *qm, *s, *beta, *Mp, *wp, *zerop;
    __half *kv0, *kv1;
    int *deg, *rowstart, *cursor, *esrc;
    cudaGetSymbolAddress((void**)&h,        g_h);
    cudaGetSymbolAddress((void**)&qm,       g_q);
    cudaGetSymbolAddress((void**)&s,        g_s);
    cudaGetSymbolAddress((void**)&beta,     g_beta);
    cudaGetSymbolAddress((void**)&Mp,       g_M);
    cudaGetSymbolAddress((void**)&wp,       g_w);
    cudaGetSymbolAddress((void**)&zerop,    g_zero);
    cudaGetSymbolAddress((void**)&kv0,      g_kv0);
    cudaGetSymbolAddress((void**)&kv1,      g_kv1);
    cudaGetSymbolAddress((void**)&deg,      g_deg);
    cudaGetSymbolAddress((void**)&rowstart, g_rowstart);
    cudaGetSymbolAddress((void**)&cursor,   g_cursor);
    cudaGetSymbolAddress((void**)&esrc,     g_esrc);

    cudaFuncSetAttribute(gemm3,    cudaFuncAttributeMaxDynamicSharedMemorySize, GEMM_SMEM);
    cudaFuncSetAttribute(prep_all, cudaFuncAttributeMaxDynamicSharedMemorySize, PREP_SMEM);

    const int GB  = (N_NODES + 127) / 128;
    const int NB  = (N_NODES + 255) / 256;
    const int ETB = (E_EDGES + 255) / 256;
    const int WNB = (N_NODES + 7) / 8;

    // ---- weights-only prep for all layers (one launch) ----
    prep_all<<<64, 256, PREP_SMEM>>>(Wq, Wk, bq);

    // ---- CSR build ----
    csr_zero<<<NB, 256>>>(deg);
    csr_count<<<ETB, 256>>>(ei, deg);
    csr_scan<<<1, 1024>>>(deg, rowstart, cursor);
    csr_scatter<<<ETB, 256>>>(ei, cursor, esrc);

    // ---- input projection: h = x@lin_W + lin_b (fp32 + dual fp16 into kv0 h-part) ----
    gemm3<<<dim3(GB, 1), 256, GEMM_SMEM>>>(
        x, lin_W, lin_W, lin_W, lin_b, lin_b, lin_b,
        h, kv0, h, kv0, nullptr, nullptr, N_NODES);

    for (int l = 0; l < NLAYERS; l++) {
        const float* Wv_l = Wv  + (size_t)l * HD * HD;
        const float* Ws_l = Wsk + (size_t)l * HD * HD;
        const float* bv_l = bv  + (size_t)l * HD;
        const float* bs_l = bsk + (size_t)l * HD;

        __half* kv_cur  = (l & 1) ? kv1 : kv0;
        __half* kv_next = (l & 1) ? kv0 : kv1;

        // 3 GEMMs + beta in one launch: qm = h@M_l, v16 -> kv_cur, s = h@Ws
        gemm3<<<dim3(GB, 3), 256, GEMM_SMEM>>>(
            h, Mp + (size_t)l * HD * HD, Wv_l, Ws_l, zerop, bv_l, bs_l,
            qm, kv_cur, s, nullptr, wp + (size_t)l * HD, beta, N_NODES);

        gat_node<<<WNB, 256>>>(rowstart, esrc, qm, kv_cur, beta, s, h, kv_next,
                               (l < NLAYERS - 1) ? 1 : 0);
    }

    classifier<<<WNB, 256>>>(h, fcW, fcb, out);
}